// round 10
// baseline (speedup 1.0000x reference)
#include <cuda_runtime.h>
#include <cuda_bf16.h>
#include <stdint.h>

// ---------------------------------------------------------------------------
// DynamicPointConvBackBone, mma.sync bf16-split edition, 16-warp variant.
// D[8192,128] = gather(A)[8192,1728] @ W[1728,128]:
//   A = Ah + Al, W = Wh + Wl (bf16);  D ~= Ah*Wh + Ah*Wl + Al*Wh  (f32 accum)
// 128 CTAs x 512 thr, CTA tile 64 rows x 128 cols, chunk = 1 neighbor (K=64).
// W pre-swizzled+split -> one cp.async.bulk per 16KB chunk, double-buffered.
// Warp tile 16x32 (4M x 4N warps), mma.sync.m16n8k16, f32 regs.
// ---------------------------------------------------------------------------

#define K3      27
#define CIN     64
#define COUT    128
#define KP      2048
#define KP_LOG2 11
#define TR      64
#define NT      512
#define EPS     1e-3f

#define SW128(o) ((o) ^ (((o) >> 3) & 0x70))

// ---- dynamic smem layout (bytes) ----
#define SM_MBAR   0        // 2 x 8B
#define SM_NL     32
#define SM_SRC    64       // 64 ints
#define SM_VAL    320
#define SM_GAMMA  576      // 128 f32
#define SM_BETA   1088
#define SM_IDX    1600     // 64*27*4 = 6912
#define SM_STAGE0 16384
#define STG_SZ    49152    // Ahi 8K | Alo 8K | Bhi 16K | Blo 16K
#define OFF_AHI   0
#define OFF_ALO   8192
#define OFF_BHI   16384
#define OFF_BLO   32768
#define SMEM_TOTAL (SM_STAGE0 + 2 * STG_SZ)   // 114688

// W packed: [chunk][split][16KB pre-swizzled bf16 tile: n rows x 64 k]
__device__ __align__(1024) uint8_t g_Wpk[K3][2][16384];

__device__ __forceinline__ uint32_t smem_u32(const void* p) {
    uint32_t a;
    asm("{ .reg .u64 t; cvta.to.shared.u64 t, %1; cvt.u32.u64 %0, t; }"
        : "=r"(a) : "l"(p));
    return a;
}
__device__ __forceinline__ void mbar_init(uint32_t a, uint32_t cnt) {
    asm volatile("mbarrier.init.shared.b64 [%0], %1;" :: "r"(a), "r"(cnt) : "memory");
}
__device__ __forceinline__ void mbar_inval(uint32_t a) {
    asm volatile("mbarrier.inval.shared.b64 [%0];" :: "r"(a) : "memory");
}
__device__ __forceinline__ void mbar_expect_tx(uint32_t a, uint32_t tx) {
    asm volatile("mbarrier.arrive.expect_tx.shared.b64 _, [%0], %1;"
                 :: "r"(a), "r"(tx) : "memory");
}
__device__ __forceinline__ void mbar_wait(uint32_t a, uint32_t parity) {
    asm volatile(
        "{\n\t.reg .pred P;\n\t"
        "W_%=:\n\t"
        "mbarrier.try_wait.parity.acquire.cta.shared::cta.b64 P, [%0], %1, 0x989680;\n\t"
        "@P bra D_%=;\n\t"
        "bra.uni W_%=;\n\t"
        "D_%=:\n\t}"
        :: "r"(a), "r"(parity) : "memory");
}
__device__ __forceinline__ void bulk_g2s(uint32_t dst, const void* src,
                                         uint32_t bytes, uint32_t mbar) {
    asm volatile(
        "cp.async.bulk.shared::cta.global.mbarrier::complete_tx::bytes "
        "[%0], [%1], %2, [%3];"
        :: "r"(dst), "l"(src), "r"(bytes), "r"(mbar) : "memory");
}
#define LDSM4(r0, r1, r2, r3, addr) \
    asm volatile("ldmatrix.sync.aligned.m8n8.x4.shared.b16 {%0,%1,%2,%3}, [%4];" \
                 : "=r"(r0), "=r"(r1), "=r"(r2), "=r"(r3) : "r"(addr))
#define MMA16816(d, a, b) \
    asm volatile("mma.sync.aligned.m16n8k16.row.col.f32.bf16.bf16.f32 " \
                 "{%0,%1,%2,%3}, {%4,%5,%6,%7}, {%8,%9}, {%0,%1,%2,%3};" \
                 : "+f"((d)[0]), "+f"((d)[1]), "+f"((d)[2]), "+f"((d)[3]) \
                 : "r"((a)[0]), "r"((a)[1]), "r"((a)[2]), "r"((a)[3]), \
                   "r"((b)[0]), "r"((b)[1]))

// split f32 pair -> bf16x2 hi + bf16x2 lo (lower half = first element)
__device__ __forceinline__ void cvt_split(float a, float b, uint32_t& hi, uint32_t& lo) {
    asm("cvt.rn.bf16x2.f32 %0, %1, %2;" : "=r"(hi) : "f"(b), "f"(a));
    float ha = __uint_as_float(hi << 16);
    float hb = __uint_as_float(hi & 0xffff0000u);
    float da = a - ha, db = b - hb;
    asm("cvt.rn.bf16x2.f32 %0, %1, %2;" : "=r"(lo) : "f"(db), "f"(da));
}

// ---------------- prep: W[k][n] f32 -> g_Wpk[c][sp][SW128(n*128+k*2)] --------
__global__ void prep_w(const float* __restrict__ W) {
    int i = blockIdx.x * blockDim.x + threadIdx.x;
    if (i >= K3 * 64 * COUT) return;
    int n = i & 127;
    int k = (i >> 7) & 63;
    int c = i >> 13;
    float w = W[(size_t)(c * 64 + k) * COUT + n];
    __nv_bfloat16 h = __float2bfloat16(w);
    __nv_bfloat16 l = __float2bfloat16(w - __bfloat162float(h));
    uint32_t off = SW128((uint32_t)(n * 128 + k * 2));
    *(__nv_bfloat16*)(&g_Wpk[c][0][off]) = h;
    *(__nv_bfloat16*)(&g_Wpk[c][1][off]) = l;
}

// ---------------- main fused kernel ----------------
__global__ __launch_bounds__(NT, 1)
void fused_mma_ln(const float* __restrict__ feat,
                  const int* __restrict__ vidx,
                  const float* __restrict__ gamma,
                  const float* __restrict__ beta,
                  const int* __restrict__ num_list,
                  const float* __restrict__ cc,
                  float* __restrict__ out_feat,
                  float* __restrict__ out_coor,
                  int Nfeat, int M, int B, int totalRows)
{
    extern __shared__ char dsm[];
    const uint32_t smb = smem_u32(dsm);
    const int tid  = threadIdx.x;
    const int wid  = tid >> 5;
    const int lane = tid & 31;
    const int base = blockIdx.x * TR;

    int* const nl_s  = (int*)(dsm + SM_NL);
    int* const src_s = (int*)(dsm + SM_SRC);
    int* const val_s = (int*)(dsm + SM_VAL);
    int* const idx_s = (int*)(dsm + SM_IDX);

    if (tid == 0) {
        mbar_init(smb + SM_MBAR + 0, 1);
        mbar_init(smb + SM_MBAR + 8, 1);
        #pragma unroll 4
        for (int i = 0; i < B && i < 8; ++i) nl_s[i] = num_list[i];
    }
    if (tid < COUT) {
        ((float*)(dsm + SM_GAMMA))[tid] = gamma[tid];
        ((float*)(dsm + SM_BETA))[tid]  = beta[tid];
    }
    __syncthreads();

    // --- per-row source voxel + validity ------------------------------------
    if (tid < TR) {
        int gr = base + tid;
        int b = gr >> KP_LOG2;
        int j = gr & (KP - 1);
        int off = 0;
        #pragma unroll 4
        for (int i = 0; i < b; ++i) off += nl_s[i];
        int nl = nl_s[b];
        int src = off + j;
        if (src > M - 1) src = M - 1;
        if (src < 0)     src = 0;
        src_s[tid] = src;
        val_s[tid] = (j < nl) ? 1 : 0;
    }
    __syncthreads();

    // --- neighbor indices ---------------------------------------------------
    for (int e = tid; e < TR * K3; e += NT) {
        int r = e / K3, k = e - r * K3;
        int raw = vidx[(size_t)src_s[r] * K3 + k];
        int v = raw;
        if (raw < 0) v = -1;
        else if (v > Nfeat - 1) v = Nfeat - 1;
        idx_s[e] = v;
    }
    __syncthreads();

    // --- kick off B bulk copies for chunks 0,1 ------------------------------
    if (tid == 0) {
        #pragma unroll
        for (int s = 0; s < 2; ++s) {
            uint32_t mb = smb + SM_MBAR + s * 8;
            uint32_t bd = smb + SM_STAGE0 + s * STG_SZ;
            mbar_expect_tx(mb, 32768);
            bulk_g2s(bd + OFF_BHI, g_Wpk[s][0], 16384, mb);
            bulk_g2s(bd + OFF_BLO, g_Wpk[s][1], 16384, mb);
        }
    }

    // --- A gather mapping: row = tid>>3, eighth q = tid&7 (8 channels) ------
    const int g_row = tid >> 3;
    const int g_q   = tid & 7;

    float4 areg[2];
    {
        int fid = idx_s[g_row * K3 + 0];
        const float4* src = (fid >= 0)
            ? (const float4*)(feat + (size_t)fid * CIN + g_q * 8) : nullptr;
        areg[0] = src ? src[0] : make_float4(0.f, 0.f, 0.f, 0.f);
        areg[1] = src ? src[1] : make_float4(0.f, 0.f, 0.f, 0.f);
    }

    // --- warp tiling: 4M x 4N, warp tile 16 rows x 32 cols ------------------
    const int wm = wid & 3;           // rows wm*16 .. +15
    const int wn = wid >> 2;          // cols wn*32 .. +31
    const int m_  = lane >> 3;        // ldmatrix matrix id
    const int ri  = lane & 7;

    // A frag: row = wm*16 + (m&1)*8 + ri ; kb = ks*32 + ((lane>>4)&1)*16
    const uint32_t arow = (uint32_t)(wm * 16 + (m_ & 1) * 8 + ri) * 128;
    const uint32_t axor = (arow >> 3) & 0x70;
    const uint32_t akc  = ((lane >> 4) & 1) * 16;
    // B frag: n = wn*32 + pt*16 + ((lane>>4)&1)*8 + ri ; kb = ks*32 + ((lane>>3)&1)*16
    uint32_t brow[2], bxor[2];
    #pragma unroll
    for (int pt = 0; pt < 2; ++pt) {
        uint32_t rp = (uint32_t)(wn * 32 + pt * 16 + ((lane >> 4) & 1) * 8 + ri) * 128;
        brow[pt] = rp;
        bxor[pt] = (rp >> 3) & 0x70;
    }
    const uint32_t bkc = ((lane >> 3) & 1) * 16;

    float acc[4][4];                  // [nt][reg]
    #pragma unroll
    for (int nt = 0; nt < 4; ++nt)
        #pragma unroll
        for (int r = 0; r < 4; ++r) acc[nt][r] = 0.f;

    for (int c = 0; c < K3; ++c) {
        const int s = c & 1;
        const uint32_t stg = smb + SM_STAGE0 + s * STG_SZ;

        // STS A(c) from prefetch regs: bf16 hi/lo, swizzled
        {
            uint32_t h[4], l[4];
            cvt_split(areg[0].x, areg[0].y, h[0], l[0]);
            cvt_split(areg[0].z, areg[0].w, h[1], l[1]);
            cvt_split(areg[1].x, areg[1].y, h[2], l[2]);
            cvt_split(areg[1].z, areg[1].w, h[3], l[3]);
            uint32_t o = SW128((uint32_t)(g_row * 128 + g_q * 16));
            *(uint4*)(dsm + SM_STAGE0 + s * STG_SZ + OFF_AHI + o) =
                make_uint4(h[0], h[1], h[2], h[3]);
            *(uint4*)(dsm + SM_STAGE0 + s * STG_SZ + OFF_ALO + o) =
                make_uint4(l[0], l[1], l[2], l[3]);
        }
        // prefetch A regs for chunk c+1
        if (c + 1 < K3) {
            int fid = idx_s[g_row * K3 + c + 1];
            const float4* src = (fid >= 0)
                ? (const float4*)(feat + (size_t)fid * CIN + g_q * 8) : nullptr;
            areg[0] = src ? src[0] : make_float4(0.f, 0.f, 0.f, 0.f);
            areg[1] = src ? src[1] : make_float4(0.f, 0.f, 0.f, 0.f);
        }
        __syncthreads();                       // A(c) visible to all warps
        mbar_wait(smb + SM_MBAR + s * 8, (c >> 1) & 1);   // B(c) arrived

        // compute: 4 k16-steps
        const uint32_t Ah = stg + OFF_AHI, Al = stg + OFF_ALO;
        const uint32_t Bh = stg + OFF_BHI, Bl = stg + OFF_BLO;
        #pragma unroll
        for (int ks = 0; ks < 4; ++ks) {
            uint32_t ah[4], al[4], bh[4][2], bl[4][2];
            const uint32_t akb = ks * 32 + akc;
            const uint32_t bkb = ks * 32 + bkc;
            LDSM4(ah[0], ah[1], ah[2], ah[3], Ah + arow + (akb ^ axor));
            LDSM4(al[0], al[1], al[2], al[3], Al + arow + (akb ^ axor));
            #pragma unroll
            for (int pt = 0; pt < 2; ++pt) {
                LDSM4(bh[2*pt][0], bh[2*pt][1], bh[2*pt+1][0], bh[2*pt+1][1],
                      Bh + brow[pt] + (bkb ^ bxor[pt]));
                LDSM4(bl[2*pt][0], bl[2*pt][1], bl[2*pt+1][0], bl[2*pt+1][1],
                      Bl + brow[pt] + (bkb ^ bxor[pt]));
            }
            #pragma unroll
            for (int nt = 0; nt < 4; ++nt) {
                MMA16816(acc[nt], ah, bh[nt]);
                MMA16816(acc[nt], ah, bl[nt]);
                MMA16816(acc[nt], al, bh[nt]);
            }
        }
        __syncthreads();                       // stage s free
        if (tid == 0 && c + 2 < K3) {          // refill stage s with chunk c+2
            uint32_t mb = smb + SM_MBAR + s * 8;
            mbar_expect_tx(mb, 32768);
            bulk_g2s(stg + OFF_BHI, g_Wpk[c + 2][0], 16384, mb);
            bulk_g2s(stg + OFF_BLO, g_Wpk[c + 2][1], 16384, mb);
        }
    }

    // --- spill accumulators to smem (reuse stage0: 32KB) --------------------
    float* const Red = (float*)(dsm + SM_STAGE0);
    {
        int r0 = wm * 16 + (lane >> 2);
        #pragma unroll
        for (int nt = 0; nt < 4; ++nt) {
            int cbase = wn * 32 + nt * 8 + (lane & 3) * 2;
            *(float2*)(Red + r0 * COUT + cbase) =
                make_float2(acc[nt][0], acc[nt][1]);
            *(float2*)(Red + (r0 + 8) * COUT + cbase) =
                make_float2(acc[nt][2], acc[nt][3]);
        }
    }
    __syncthreads();

    // --- LayerNorm + ReLU: row = tid>>3, q = tid&7 (16 cols each) -----------
    {
        const int row = tid >> 3;
        const int q   = tid & 7;
        const float* rrow = Red + row * COUT + q * 16;
        float4 v[4];
        float s = 0.f, sq = 0.f;
        #pragma unroll
        for (int i = 0; i < 4; ++i) {
            v[i] = ((const float4*)rrow)[i];
            s  += v[i].x + v[i].y + v[i].z + v[i].w;
            sq += v[i].x*v[i].x + v[i].y*v[i].y + v[i].z*v[i].z + v[i].w*v[i].w;
        }
        s  += __shfl_xor_sync(0xffffffffu, s, 1);
        sq += __shfl_xor_sync(0xffffffffu, sq, 1);
        s  += __shfl_xor_sync(0xffffffffu, s, 2);
        sq += __shfl_xor_sync(0xffffffffu, sq, 2);
        s  += __shfl_xor_sync(0xffffffffu, s, 4);
        sq += __shfl_xor_sync(0xffffffffu, sq, 4);
        float mu  = s * (1.f / COUT);
        float var = sq * (1.f / COUT) - mu * mu;
        float inv = rsqrtf(var + EPS);
        int valid = val_s[row];
        int gr = base + row;
        const float* gs = (const float*)(dsm + SM_GAMMA) + q * 16;
        const float* bs = (const float*)(dsm + SM_BETA)  + q * 16;
        float* orow = out_feat + (size_t)gr * COUT + q * 16;
        #pragma unroll
        for (int i = 0; i < 4; ++i) {
            float4 o;
            o.x = fmaxf(0.f, (v[i].x - mu) * inv * gs[4*i+0] + bs[4*i+0]);
            o.y = fmaxf(0.f, (v[i].y - mu) * inv * gs[4*i+1] + bs[4*i+1]);
            o.z = fmaxf(0.f, (v[i].z - mu) * inv * gs[4*i+2] + bs[4*i+2]);
            o.w = fmaxf(0.f, (v[i].w - mu) * inv * gs[4*i+3] + bs[4*i+3]);
            if (!valid) o = make_float4(0.f, 0.f, 0.f, 0.f);
            ((float4*)orow)[i] = o;
        }
    }

    // --- coords (col0 unconditional per reference quirk; xyz masked) --------
    if (tid < TR) {
        int gr = base + tid;
        int b  = gr >> KP_LOG2;
        int src = src_s[tid];
        float col0 = (b < B - 1) ? (float)(b + 1) : 0.f;
        float4 o;
        o.x = col0;
        if (val_s[tid]) {
            o.y = cc[(size_t)src * 3 + 0];
            o.z = cc[(size_t)src * 3 + 1];
            o.w = cc[(size_t)src * 3 + 2];
        } else {
            o.y = 0.f; o.z = 0.f; o.w = 0.f;
        }
        ((float4*)out_coor)[gr] = o;
    }

    __syncthreads();
    if (tid == 0) { mbar_inval(smb + SM_MBAR + 0); mbar_inval(smb + SM_MBAR + 8); }
}

extern "C" void kernel_launch(void* const* d_in, const int* in_sizes, int n_in,
                              void* d_out, int out_size)
{
    const float* feat     = (const float*)d_in[0];
    const float* cc       = (const float*)d_in[1];
    const int*   vidx     = (const int*)d_in[2];     // int32 (JAX x64 disabled)
    const int*   num_list = (const int*)d_in[3];
    const float* W        = (const float*)d_in[4];
    const float* gamma    = (const float*)d_in[5];
    const float* beta     = (const float*)d_in[6];

    int Nfeat = in_sizes[0] / CIN;   // 200000
    int M     = in_sizes[1] / 3;     // 40000
    int B     = in_sizes[3];         // 4
    int totalRows = B * KP;          // 8192

    float* out_feat = (float*)d_out;
    float* out_coor = out_feat + (size_t)totalRows * COUT;

    cudaFuncSetAttribute(fused_mma_ln,
                         cudaFuncAttributeMaxDynamicSharedMemorySize, SMEM_TOTAL);

    prep_w<<<(K3 * 64 * COUT + 255) / 256, 256>>>(W);
    fused_mma_ln<<<totalRows / TR, NT, SMEM_TOTAL>>>(feat, vidx, gamma, beta,
                                                     num_list, cc, out_feat,
                                                     out_coor, Nfeat, M, B,
                                                     totalRows);
}

// round 11
// speedup vs baseline: 1.1507x; 1.1507x over previous
#include <cuda_runtime.h>
#include <cuda_bf16.h>
#include <stdint.h>

// ---------------------------------------------------------------------------
// DynamicPointConvBackBone, mma.sync bf16-split, pipelined edition.
// D[8192,128] = gather(A)[8192,1728] @ W[1728,128]:
//   A = Ah + Al, W = Wh + Wl (bf16);  D ~= Ah*Wh + Ah*Wl + Al*Wh  (f32 accum)
// 128 CTAs x 256 thr (8 warps, warp tile 32x32), chunk = 1 neighbor (K=64).
// B: 4-stage cp.async.bulk pipeline (refill c+3 at iter c). A: 2-stage STS.
// ONE __syncthreads per chunk (bar(c) already orders compute(c-1) before any
// overwrite of stage buffers). Epilogue: smem-spill LayerNorm + ReLU + coords.
// ---------------------------------------------------------------------------

#define K3      27
#define CIN     64
#define COUT    128
#define KP      2048
#define KP_LOG2 11
#define TR      64
#define NT      256
#define EPS     1e-3f

#define SW128(o) ((o) ^ (((o) >> 3) & 0x70))

// ---- dynamic smem layout (bytes) ----
#define SM_MBAR   0        // 4 x 8B
#define SM_NL     64
#define SM_SRC    96       // 64 ints
#define SM_VAL    352
#define SM_GAMMA  608      // 128 f32
#define SM_BETA   1120
#define SM_IDX    1632     // 64*27*4 = 6912
#define SM_A0     16384    // 2 stages x 16KB (Ahi @+0, Alo @+8192)
#define A_STG     16384
#define SM_B0     49152    // 4 stages x 32KB (Bhi @+0, Blo @+16384)
#define B_STG     32768
#define SMEM_TOTAL (SM_B0 + 4 * B_STG)   // 180224

// W packed: [chunk][split][16KB pre-swizzled bf16 tile: n rows x 64 k]
__device__ __align__(1024) uint8_t g_Wpk[K3][2][16384];

__device__ __forceinline__ uint32_t smem_u32(const void* p) {
    uint32_t a;
    asm("{ .reg .u64 t; cvta.to.shared.u64 t, %1; cvt.u32.u64 %0, t; }"
        : "=r"(a) : "l"(p));
    return a;
}
__device__ __forceinline__ void mbar_init(uint32_t a, uint32_t cnt) {
    asm volatile("mbarrier.init.shared.b64 [%0], %1;" :: "r"(a), "r"(cnt) : "memory");
}
__device__ __forceinline__ void mbar_inval(uint32_t a) {
    asm volatile("mbarrier.inval.shared.b64 [%0];" :: "r"(a) : "memory");
}
__device__ __forceinline__ void mbar_expect_tx(uint32_t a, uint32_t tx) {
    asm volatile("mbarrier.arrive.expect_tx.shared.b64 _, [%0], %1;"
                 :: "r"(a), "r"(tx) : "memory");
}
__device__ __forceinline__ void mbar_wait(uint32_t a, uint32_t parity) {
    asm volatile(
        "{\n\t.reg .pred P;\n\t"
        "W_%=:\n\t"
        "mbarrier.try_wait.parity.acquire.cta.shared::cta.b64 P, [%0], %1, 0x989680;\n\t"
        "@P bra D_%=;\n\t"
        "bra.uni W_%=;\n\t"
        "D_%=:\n\t}"
        :: "r"(a), "r"(parity) : "memory");
}
__device__ __forceinline__ void bulk_g2s(uint32_t dst, const void* src,
                                         uint32_t bytes, uint32_t mbar) {
    asm volatile(
        "cp.async.bulk.shared::cta.global.mbarrier::complete_tx::bytes "
        "[%0], [%1], %2, [%3];"
        :: "r"(dst), "l"(src), "r"(bytes), "r"(mbar) : "memory");
}
#define LDSM4(r0, r1, r2, r3, addr) \
    asm volatile("ldmatrix.sync.aligned.m8n8.x4.shared.b16 {%0,%1,%2,%3}, [%4];" \
                 : "=r"(r0), "=r"(r1), "=r"(r2), "=r"(r3) : "r"(addr))
#define MMA16816(d, a, b) \
    asm volatile("mma.sync.aligned.m16n8k16.row.col.f32.bf16.bf16.f32 " \
                 "{%0,%1,%2,%3}, {%4,%5,%6,%7}, {%8,%9}, {%0,%1,%2,%3};" \
                 : "+f"((d)[0]), "+f"((d)[1]), "+f"((d)[2]), "+f"((d)[3]) \
                 : "r"((a)[0]), "r"((a)[1]), "r"((a)[2]), "r"((a)[3]), \
                   "r"((b)[0]), "r"((b)[1]))

// split f32 pair -> bf16x2 hi + bf16x2 lo (lower half = first element)
__device__ __forceinline__ void cvt_split(float a, float b, uint32_t& hi, uint32_t& lo) {
    asm("cvt.rn.bf16x2.f32 %0, %1, %2;" : "=r"(hi) : "f"(b), "f"(a));
    float ha = __uint_as_float(hi << 16);
    float hb = __uint_as_float(hi & 0xffff0000u);
    float da = a - ha, db = b - hb;
    asm("cvt.rn.bf16x2.f32 %0, %1, %2;" : "=r"(lo) : "f"(db), "f"(da));
}

// ---------------- prep: W[k][n] f32 -> g_Wpk via smem transpose --------------
// grid = 27 (one chunk each), block = 256. Coalesced loads AND stores.
__global__ void prep_w(const float* __restrict__ W) {
    __shared__ float sw[64 * 129];           // padded stride vs bank conflicts
    const int c   = blockIdx.x;
    const int tid = threadIdx.x;
    const float2* src = (const float2*)(W + (size_t)c * 64 * COUT);
    for (int i = tid; i < 64 * COUT / 2; i += 256) {
        float2 v = src[i];
        int k = (2 * i) >> 7, n = (2 * i) & 127;
        sw[k * 129 + n]     = v.x;
        sw[k * 129 + n + 1] = v.y;
    }
    __syncthreads();
    for (int t = tid; t < 1024; t += 256) {  // kh fast -> coalesced 16B stores
        int kh = t & 7, n = t >> 3;
        uint32_t h[4], l[4];
        #pragma unroll
        for (int i = 0; i < 4; ++i) {
            float a = sw[(kh * 8 + 2 * i)     * 129 + n];
            float b = sw[(kh * 8 + 2 * i + 1) * 129 + n];
            cvt_split(a, b, h[i], l[i]);
        }
        uint32_t off = SW128((uint32_t)(n * 128 + kh * 16));
        *(uint4*)(&g_Wpk[c][0][off]) = make_uint4(h[0], h[1], h[2], h[3]);
        *(uint4*)(&g_Wpk[c][1][off]) = make_uint4(l[0], l[1], l[2], l[3]);
    }
}

// ---------------- main fused kernel ----------------
__global__ __launch_bounds__(NT, 1)
void fused_mma_ln(const float* __restrict__ feat,
                  const int* __restrict__ vidx,
                  const float* __restrict__ gamma,
                  const float* __restrict__ beta,
                  const int* __restrict__ num_list,
                  const float* __restrict__ cc,
                  float* __restrict__ out_feat,
                  float* __restrict__ out_coor,
                  int Nfeat, int M, int B, int totalRows)
{
    extern __shared__ char dsm[];
    const uint32_t smb = smem_u32(dsm);
    const int tid  = threadIdx.x;
    const int wid  = tid >> 5;
    const int lane = tid & 31;
    const int base = blockIdx.x * TR;

    int* const nl_s  = (int*)(dsm + SM_NL);
    int* const src_s = (int*)(dsm + SM_SRC);
    int* const val_s = (int*)(dsm + SM_VAL);
    int* const idx_s = (int*)(dsm + SM_IDX);

    if (tid == 0) {
        #pragma unroll
        for (int s = 0; s < 4; ++s) mbar_init(smb + SM_MBAR + s * 8, 1);
        #pragma unroll 4
        for (int i = 0; i < B && i < 8; ++i) nl_s[i] = num_list[i];
    }
    if (tid < COUT) {
        ((float*)(dsm + SM_GAMMA))[tid] = gamma[tid];
        ((float*)(dsm + SM_BETA))[tid]  = beta[tid];
    }
    __syncthreads();

    // --- per-row source voxel + validity ------------------------------------
    if (tid < TR) {
        int gr = base + tid;
        int b = gr >> KP_LOG2;
        int j = gr & (KP - 1);
        int off = 0;
        #pragma unroll 4
        for (int i = 0; i < b; ++i) off += nl_s[i];
        int nl = nl_s[b];
        int src = off + j;
        if (src > M - 1) src = M - 1;
        if (src < 0)     src = 0;
        src_s[tid] = src;
        val_s[tid] = (j < nl) ? 1 : 0;
    }
    __syncthreads();

    // --- neighbor indices ---------------------------------------------------
    for (int e = tid; e < TR * K3; e += NT) {
        int r = e / K3, k = e - r * K3;
        int raw = vidx[(size_t)src_s[r] * K3 + k];
        int v = raw;
        if (raw < 0) v = -1;
        else if (v > Nfeat - 1) v = Nfeat - 1;
        idx_s[e] = v;
    }
    __syncthreads();

    // --- kick off B bulk copies for chunks 0..3 -----------------------------
    if (tid == 0) {
        #pragma unroll
        for (int s = 0; s < 4; ++s) {
            uint32_t mb = smb + SM_MBAR + s * 8;
            uint32_t bd = smb + SM_B0 + s * B_STG;
            mbar_expect_tx(mb, 32768);
            bulk_g2s(bd,         g_Wpk[s][0], 16384, mb);
            bulk_g2s(bd + 16384, g_Wpk[s][1], 16384, mb);
        }
    }

    // --- A gather mapping: row = tid>>2, quarter q = tid&3 (16 channels) ----
    const int g_row = tid >> 2;
    const int g_q   = tid & 3;

    float4 areg[4];
    {
        int fid = idx_s[g_row * K3 + 0];
        const float4* src = (fid >= 0)
            ? (const float4*)(feat + (size_t)fid * CIN + g_q * 16) : nullptr;
        #pragma unroll
        for (int i = 0; i < 4; ++i)
            areg[i] = src ? src[i] : make_float4(0.f, 0.f, 0.f, 0.f);
    }

    // --- warp tiling: 2M x 4N, warp tile 32 rows x 32 cols ------------------
    const int wm = wid & 1;           // rows wm*32 .. +31
    const int wn = wid >> 1;          // cols wn*32 .. +31
    const int m_  = lane >> 3;        // ldmatrix matrix id
    const int ri  = lane & 7;

    // A frag: row = wm*32 + mt*16 + (m&1)*8 + ri ; kb = ks*32 + ((lane>>4)&1)*16
    uint32_t arow[2], axor[2];
    #pragma unroll
    for (int mt = 0; mt < 2; ++mt) {
        uint32_t rp = (uint32_t)(wm * 32 + mt * 16 + (m_ & 1) * 8 + ri) * 128;
        arow[mt] = rp;
        axor[mt] = (rp >> 3) & 0x70;
    }
    const uint32_t akc = ((lane >> 4) & 1) * 16;
    // B frag: n = wn*32 + pt*16 + ((lane>>4)&1)*8 + ri ; kb = ks*32 + ((lane>>3)&1)*16
    uint32_t brow[2], bxor[2];
    #pragma unroll
    for (int pt = 0; pt < 2; ++pt) {
        uint32_t rp = (uint32_t)(wn * 32 + pt * 16 + ((lane >> 4) & 1) * 8 + ri) * 128;
        brow[pt] = rp;
        bxor[pt] = (rp >> 3) & 0x70;
    }
    const uint32_t bkc = ((lane >> 3) & 1) * 16;

    float acc[2][4][4];               // [mt][nt][reg]
    #pragma unroll
    for (int mt = 0; mt < 2; ++mt)
        #pragma unroll
        for (int nt = 0; nt < 4; ++nt)
            #pragma unroll
            for (int r = 0; r < 4; ++r) acc[mt][nt][r] = 0.f;

    for (int c = 0; c < K3; ++c) {
        const uint32_t Astg = smb + SM_A0 + (c & 1) * A_STG;
        const uint32_t Bstg = smb + SM_B0 + (c & 3) * B_STG;

        // STS A(c) from prefetch regs: bf16 hi/lo, swizzled
        {
            uint32_t h[8], l[8];
            #pragma unroll
            for (int i = 0; i < 4; ++i) {
                cvt_split(areg[i].x, areg[i].y, h[2*i],   l[2*i]);
                cvt_split(areg[i].z, areg[i].w, h[2*i+1], l[2*i+1]);
            }
            uint32_t o0 = SW128((uint32_t)(g_row * 128 + g_q * 32));
            uint32_t o1 = SW128((uint32_t)(g_row * 128 + g_q * 32 + 16));
            char* Abase = dsm + SM_A0 + (c & 1) * A_STG;
            *(uint4*)(Abase + o0)        = make_uint4(h[0], h[1], h[2], h[3]);
            *(uint4*)(Abase + o1)        = make_uint4(h[4], h[5], h[6], h[7]);
            *(uint4*)(Abase + 8192 + o0) = make_uint4(l[0], l[1], l[2], l[3]);
            *(uint4*)(Abase + 8192 + o1) = make_uint4(l[4], l[5], l[6], l[7]);
        }
        // prefetch A regs for chunk c+1 (latency hidden by compute(c))
        if (c + 1 < K3) {
            int fid = idx_s[g_row * K3 + c + 1];
            const float4* src = (fid >= 0)
                ? (const float4*)(feat + (size_t)fid * CIN + g_q * 16) : nullptr;
            #pragma unroll
            for (int i = 0; i < 4; ++i)
                areg[i] = src ? src[i] : make_float4(0.f, 0.f, 0.f, 0.f);
        }

        // single barrier: makes A(c) visible AND proves all warps finished
        // compute(c-1) (so refilling B stage (c+3)&3 == (c-1)&3 is safe).
        __syncthreads();

        if (tid == 0 && c >= 1 && c + 3 < K3) {
            int cc = c + 3;
            uint32_t mb = smb + SM_MBAR + (cc & 3) * 8;
            uint32_t bd = smb + SM_B0 + (cc & 3) * B_STG;
            mbar_expect_tx(mb, 32768);
            bulk_g2s(bd,         g_Wpk[cc][0], 16384, mb);
            bulk_g2s(bd + 16384, g_Wpk[cc][1], 16384, mb);
        }

        mbar_wait(smb + SM_MBAR + (c & 3) * 8, (c >> 2) & 1);   // B(c) arrived

        // compute: 4 k16-steps
        const uint32_t Ah = Astg, Al = Astg + 8192;
        const uint32_t Bh = Bstg, Bl = Bstg + 16384;
        #pragma unroll
        for (int ks = 0; ks < 4; ++ks) {
            uint32_t ah[2][4], al[2][4], bh[4][2], bl[4][2];
            const uint32_t akb = ks * 32 + akc;
            const uint32_t bkb = ks * 32 + bkc;
            #pragma unroll
            for (int mt = 0; mt < 2; ++mt) {
                LDSM4(ah[mt][0], ah[mt][1], ah[mt][2], ah[mt][3],
                      Ah + arow[mt] + (akb ^ axor[mt]));
                LDSM4(al[mt][0], al[mt][1], al[mt][2], al[mt][3],
                      Al + arow[mt] + (akb ^ axor[mt]));
            }
            #pragma unroll
            for (int pt = 0; pt < 2; ++pt) {
                LDSM4(bh[2*pt][0], bh[2*pt][1], bh[2*pt+1][0], bh[2*pt+1][1],
                      Bh + brow[pt] + (bkb ^ bxor[pt]));
                LDSM4(bl[2*pt][0], bl[2*pt][1], bl[2*pt+1][0], bl[2*pt+1][1],
                      Bl + brow[pt] + (bkb ^ bxor[pt]));
            }
            #pragma unroll
            for (int mt = 0; mt < 2; ++mt)
                #pragma unroll
                for (int nt = 0; nt < 4; ++nt) {
                    MMA16816(acc[mt][nt], ah[mt], bh[nt]);
                    MMA16816(acc[mt][nt], ah[mt], bl[nt]);
                    MMA16816(acc[mt][nt], al[mt], bh[nt]);
                }
        }
    }

    // --- spill accumulators to smem (reuse A area: exactly 32KB) ------------
    __syncthreads();
    float* const Red = (float*)(dsm + SM_A0);
    {
        #pragma unroll
        for (int mt = 0; mt < 2; ++mt) {
            int r0 = wm * 32 + mt * 16 + (lane >> 2);
            #pragma unroll
            for (int nt = 0; nt < 4; ++nt) {
                int cbase = wn * 32 + nt * 8 + (lane & 3) * 2;
                *(float2*)(Red + r0 * COUT + cbase) =
                    make_float2(acc[mt][nt][0], acc[mt][nt][1]);
                *(float2*)(Red + (r0 + 8) * COUT + cbase) =
                    make_float2(acc[mt][nt][2], acc[mt][nt][3]);
            }
        }
    }
    __syncthreads();

    // --- LayerNorm + ReLU: row = tid>>2, quad q = tid&3 (32 cols) -----------
    {
        const int row = tid >> 2;
        const int q   = tid & 3;
        const float* rrow = Red + row * COUT + q * 32;
        float4 v[8];
        float s = 0.f, sq = 0.f;
        #pragma unroll
        for (int i = 0; i < 8; ++i) {
            v[i] = ((const float4*)rrow)[i];
            s  += v[i].x + v[i].y + v[i].z + v[i].w;
            sq += v[i].x*v[i].x + v[i].y*v[i].y + v[i].z*v[i].z + v[i].w*v[i].w;
        }
        s  += __shfl_xor_sync(0xffffffffu, s, 1);
        sq += __shfl_xor_sync(0xffffffffu, sq, 1);
        s  += __shfl_xor_sync(0xffffffffu, s, 2);
        sq += __shfl_xor_sync(0xffffffffu, sq, 2);
        float mu  = s * (1.f / COUT);
        float var = sq * (1.f / COUT) - mu * mu;
        float inv = rsqrtf(var + EPS);
        int valid = val_s[row];
        int gr = base + row;
        const float* gs = (const float*)(dsm + SM_GAMMA) + q * 32;
        const float* bs = (const float*)(dsm + SM_BETA)  + q * 32;
        float* orow = out_feat + (size_t)gr * COUT + q * 32;
        #pragma unroll
        for (int i = 0; i < 8; ++i) {
            float4 o;
            o.x = fmaxf(0.f, (v[i].x - mu) * inv * gs[4*i+0] + bs[4*i+0]);
            o.y = fmaxf(0.f, (v[i].y - mu) * inv * gs[4*i+1] + bs[4*i+1]);
            o.z = fmaxf(0.f, (v[i].z - mu) * inv * gs[4*i+2] + bs[4*i+2]);
            o.w = fmaxf(0.f, (v[i].w - mu) * inv * gs[4*i+3] + bs[4*i+3]);
            if (!valid) o = make_float4(0.f, 0.f, 0.f, 0.f);
            ((float4*)orow)[i] = o;
        }
    }

    // --- coords (col0 unconditional per reference quirk; xyz masked) --------
    if (tid < TR) {
        int gr = base + tid;
        int b  = gr >> KP_LOG2;
        int src = src_s[tid];
        float col0 = (b < B - 1) ? (float)(b + 1) : 0.f;
        float4 o;
        o.x = col0;
        if (val_s[tid]) {
            o.y = cc[(size_t)src * 3 + 0];
            o.z = cc[(size_t)src * 3 + 1];
            o.w = cc[(size_t)src * 3 + 2];
        } else {
            o.y = 0.f; o.z = 0.f; o.w = 0.f;
        }
        ((float4*)out_coor)[gr] = o;
    }

    __syncthreads();
    if (tid == 0) {
        #pragma unroll
        for (int s = 0; s < 4; ++s) mbar_inval(smb + SM_MBAR + s * 8);
    }
}

extern "C" void kernel_launch(void* const* d_in, const int* in_sizes, int n_in,
                              void* d_out, int out_size)
{
    const float* feat     = (const float*)d_in[0];
    const float* cc       = (const float*)d_in[1];
    const int*   vidx     = (const int*)d_in[2];     // int32 (JAX x64 disabled)
    const int*   num_list = (const int*)d_in[3];
    const float* W        = (const float*)d_in[4];
    const float* gamma    = (const float*)d_in[5];
    const float* beta     = (const float*)d_in[6];

    int Nfeat = in_sizes[0] / CIN;   // 200000
    int M     = in_sizes[1] / 3;     // 40000
    int B     = in_sizes[3];         // 4
    int totalRows = B * KP;          // 8192

    float* out_feat = (float*)d_out;
    float* out_coor = out_feat + (size_t)totalRows * COUT;

    cudaFuncSetAttribute(fused_mma_ln,
                         cudaFuncAttributeMaxDynamicSharedMemorySize, SMEM_TOTAL);

    prep_w<<<K3, 256>>>(W);
    fused_mma_ln<<<totalRows / TR, NT, SMEM_TOTAL>>>(feat, vidx, gamma, beta,
                                                     num_list, cc, out_feat,
                                                     out_coor, Nfeat, M, B,
                                                     totalRows);
}

// round 12
// speedup vs baseline: 1.2897x; 1.1208x over previous
#include <cuda_runtime.h>
#include <cuda_bf16.h>
#include <stdint.h>

// ---------------------------------------------------------------------------
// DynamicPointConvBackBone, mma.sync bf16-split, dual-group split-K edition.
// D[8192,128] = gather(A)[8192,1728] @ W[1728,128]:
//   A = Ah + Al, W = Wh + Wl (bf16);  D ~= Ah*Wh + Ah*Wl + Al*Wh  (f32 accum)
// 128 CTAs x 512 thr = 2 groups x 8 warps. Group 0: chunks 0-12, group 1:
// chunks 13-26 (chunk = 1 neighbor, K=64). Per group: 2-stage A (STS) and
// 2-stage B (cp.async.bulk) pipelines, own mbarriers + named barrier.
// Warp tile 32x32 (2M x 4N per group). Reduction in smem, 512-thread LN.
// ---------------------------------------------------------------------------

#define K3      27
#define CIN     64
#define COUT    128
#define KP      2048
#define KP_LOG2 11
#define TR      64
#define NT      512
#define EPS     1e-3f

#define SW128(o) ((o) ^ (((o) >> 3) & 0x70))

// ---- dynamic smem layout (bytes) ----
#define SM_MBAR   0        // 4 x 8B (group*2 + stage)
#define SM_NL     64
#define SM_SRC    96       // 64 ints
#define SM_VAL    352
#define SM_GAMMA  608      // 128 f32
#define SM_BETA   1120
#define SM_IDX    1632     // 64*27*4 = 6912
#define SM_A0     16384    // per group: 2 stages x 16KB (Ahi@+0, Alo@+8192)
#define A_STG     16384
#define A_GRP     32768
#define SM_B0     81920    // per group: 2 stages x 32KB (Bhi@+0, Blo@+16384)
#define B_STG     32768
#define B_GRP     65536
#define SMEM_TOTAL (SM_B0 + 2 * B_GRP)   // 212992 (208KB)

// W packed: [chunk][split][16KB pre-swizzled bf16 tile: n rows x 64 k]
__device__ __align__(1024) uint8_t g_Wpk[K3][2][16384];

__device__ __forceinline__ uint32_t smem_u32(const void* p) {
    uint32_t a;
    asm("{ .reg .u64 t; cvta.to.shared.u64 t, %1; cvt.u32.u64 %0, t; }"
        : "=r"(a) : "l"(p));
    return a;
}
__device__ __forceinline__ void mbar_init(uint32_t a, uint32_t cnt) {
    asm volatile("mbarrier.init.shared.b64 [%0], %1;" :: "r"(a), "r"(cnt) : "memory");
}
__device__ __forceinline__ void mbar_inval(uint32_t a) {
    asm volatile("mbarrier.inval.shared.b64 [%0];" :: "r"(a) : "memory");
}
__device__ __forceinline__ void mbar_expect_tx(uint32_t a, uint32_t tx) {
    asm volatile("mbarrier.arrive.expect_tx.shared.b64 _, [%0], %1;"
                 :: "r"(a), "r"(tx) : "memory");
}
__device__ __forceinline__ void mbar_wait(uint32_t a, uint32_t parity) {
    asm volatile(
        "{\n\t.reg .pred P;\n\t"
        "W_%=:\n\t"
        "mbarrier.try_wait.parity.acquire.cta.shared::cta.b64 P, [%0], %1, 0x989680;\n\t"
        "@P bra D_%=;\n\t"
        "bra.uni W_%=;\n\t"
        "D_%=:\n\t}"
        :: "r"(a), "r"(parity) : "memory");
}
__device__ __forceinline__ void bulk_g2s(uint32_t dst, const void* src,
                                         uint32_t bytes, uint32_t mbar) {
    asm volatile(
        "cp.async.bulk.shared::cta.global.mbarrier::complete_tx::bytes "
        "[%0], [%1], %2, [%3];"
        :: "r"(dst), "l"(src), "r"(bytes), "r"(mbar) : "memory");
}
#define BARG(gid) \
    asm volatile("bar.sync %0, 256;" :: "r"((gid) + 1) : "memory")
#define LDSM4(r0, r1, r2, r3, addr) \
    asm volatile("ldmatrix.sync.aligned.m8n8.x4.shared.b16 {%0,%1,%2,%3}, [%4];" \
                 : "=r"(r0), "=r"(r1), "=r"(r2), "=r"(r3) : "r"(addr))
#define MMA16816(d, a, b) \
    asm volatile("mma.sync.aligned.m16n8k16.row.col.f32.bf16.bf16.f32 " \
                 "{%0,%1,%2,%3}, {%4,%5,%6,%7}, {%8,%9}, {%0,%1,%2,%3};" \
                 : "+f"((d)[0]), "+f"((d)[1]), "+f"((d)[2]), "+f"((d)[3]) \
                 : "r"((a)[0]), "r"((a)[1]), "r"((a)[2]), "r"((a)[3]), \
                   "r"((b)[0]), "r"((b)[1]))

// split f32 pair -> bf16x2 hi + bf16x2 lo (lower half = first element)
__device__ __forceinline__ void cvt_split(float a, float b, uint32_t& hi, uint32_t& lo) {
    asm("cvt.rn.bf16x2.f32 %0, %1, %2;" : "=r"(hi) : "f"(b), "f"(a));
    float ha = __uint_as_float(hi << 16);
    float hb = __uint_as_float(hi & 0xffff0000u);
    float da = a - ha, db = b - hb;
    asm("cvt.rn.bf16x2.f32 %0, %1, %2;" : "=r"(lo) : "f"(db), "f"(da));
}

// ---------------- prep: W[k][n] f32 -> g_Wpk via smem transpose --------------
__global__ void prep_w(const float* __restrict__ W) {
    __shared__ float sw[64 * 129];
    const int c   = blockIdx.x;
    const int tid = threadIdx.x;
    const float2* src = (const float2*)(W + (size_t)c * 64 * COUT);
    for (int i = tid; i < 64 * COUT / 2; i += 256) {
        float2 v = src[i];
        int k = (2 * i) >> 7, n = (2 * i) & 127;
        sw[k * 129 + n]     = v.x;
        sw[k * 129 + n + 1] = v.y;
    }
    __syncthreads();
    for (int t = tid; t < 1024; t += 256) {
        int kh = t & 7, n = t >> 3;
        uint32_t h[4], l[4];
        #pragma unroll
        for (int i = 0; i < 4; ++i) {
            float a = sw[(kh * 8 + 2 * i)     * 129 + n];
            float b = sw[(kh * 8 + 2 * i + 1) * 129 + n];
            cvt_split(a, b, h[i], l[i]);
        }
        uint32_t off = SW128((uint32_t)(n * 128 + kh * 16));
        *(uint4*)(&g_Wpk[c][0][off]) = make_uint4(h[0], h[1], h[2], h[3]);
        *(uint4*)(&g_Wpk[c][1][off]) = make_uint4(l[0], l[1], l[2], l[3]);
    }
}

// ---------------- main fused kernel ----------------
__global__ __launch_bounds__(NT, 1)
void fused_mma_ln(const float* __restrict__ feat,
                  const int* __restrict__ vidx,
                  const float* __restrict__ gamma,
                  const float* __restrict__ beta,
                  const int* __restrict__ num_list,
                  const float* __restrict__ cc,
                  float* __restrict__ out_feat,
                  float* __restrict__ out_coor,
                  int Nfeat, int M, int B, int totalRows)
{
    extern __shared__ char dsm[];
    const uint32_t smb = smem_u32(dsm);
    const int tid  = threadIdx.x;
    const int gid  = tid >> 8;          // group 0/1
    const int ltid = tid & 255;
    const int lane = tid & 31;
    const int base = blockIdx.x * TR;

    const int CB  = gid ? 13 : 0;       // first chunk of this group
    const int NCH = gid ? 14 : 13;      // chunks in this group

    int* const nl_s  = (int*)(dsm + SM_NL);
    int* const src_s = (int*)(dsm + SM_SRC);
    int* const val_s = (int*)(dsm + SM_VAL);
    int* const idx_s = (int*)(dsm + SM_IDX);

    if (tid == 0) {
        #pragma unroll
        for (int s = 0; s < 4; ++s) mbar_init(smb + SM_MBAR + s * 8, 1);
        #pragma unroll 4
        for (int i = 0; i < B && i < 8; ++i) nl_s[i] = num_list[i];
    }
    if (tid < COUT) {
        ((float*)(dsm + SM_GAMMA))[tid] = gamma[tid];
        ((float*)(dsm + SM_BETA))[tid]  = beta[tid];
    }
    __syncthreads();

    // --- per-row source voxel + validity ------------------------------------
    if (tid < TR) {
        int gr = base + tid;
        int b = gr >> KP_LOG2;
        int j = gr & (KP - 1);
        int off = 0;
        #pragma unroll 4
        for (int i = 0; i < b; ++i) off += nl_s[i];
        int nl = nl_s[b];
        int src = off + j;
        if (src > M - 1) src = M - 1;
        if (src < 0)     src = 0;
        src_s[tid] = src;
        val_s[tid] = (j < nl) ? 1 : 0;
    }
    __syncthreads();

    // --- neighbor indices ---------------------------------------------------
    for (int e = tid; e < TR * K3; e += NT) {
        int r = e / K3, k = e - r * K3;
        int raw = vidx[(size_t)src_s[r] * K3 + k];
        int v = raw;
        if (raw < 0) v = -1;
        else if (v > Nfeat - 1) v = Nfeat - 1;
        idx_s[e] = v;
    }
    __syncthreads();

    // --- kick off this group's B copies for local chunks 0,1 ----------------
    if (ltid == 0) {
        #pragma unroll
        for (int s = 0; s < 2; ++s) {
            uint32_t mb = smb + SM_MBAR + (gid * 2 + s) * 8;
            uint32_t bd = smb + SM_B0 + gid * B_GRP + s * B_STG;
            mbar_expect_tx(mb, 32768);
            bulk_g2s(bd,         g_Wpk[CB + s][0], 16384, mb);
            bulk_g2s(bd + 16384, g_Wpk[CB + s][1], 16384, mb);
        }
    }

    // --- A gather mapping: row = ltid>>2, quarter q = ltid&3 (16 ch) --------
    const int g_row = ltid >> 2;
    const int g_q   = ltid & 3;

    float4 areg[4];
    {
        int fid = idx_s[g_row * K3 + CB];
        const float4* src = (fid >= 0)
            ? (const float4*)(feat + (size_t)fid * CIN + g_q * 16) : nullptr;
        #pragma unroll
        for (int i = 0; i < 4; ++i)
            areg[i] = src ? src[i] : make_float4(0.f, 0.f, 0.f, 0.f);
    }

    // --- warp tiling within group: 2M x 4N, warp tile 32x32 -----------------
    const int gwid = (tid >> 5) & 7;
    const int wm = gwid & 1;          // rows wm*32 .. +31
    const int wn = gwid >> 1;         // cols wn*32 .. +31
    const int m_  = lane >> 3;
    const int ri  = lane & 7;

    uint32_t arow[2], axor[2];
    #pragma unroll
    for (int mt = 0; mt < 2; ++mt) {
        uint32_t rp = (uint32_t)(wm * 32 + mt * 16 + (m_ & 1) * 8 + ri) * 128;
        arow[mt] = rp;
        axor[mt] = (rp >> 3) & 0x70;
    }
    const uint32_t akc = ((lane >> 4) & 1) * 16;
    uint32_t brow[2], bxor[2];
    #pragma unroll
    for (int pt = 0; pt < 2; ++pt) {
        uint32_t rp = (uint32_t)(wn * 32 + pt * 16 + ((lane >> 4) & 1) * 8 + ri) * 128;
        brow[pt] = rp;
        bxor[pt] = (rp >> 3) & 0x70;
    }
    const uint32_t bkc = ((lane >> 3) & 1) * 16;

    float acc[2][4][4];               // [mt][nt][reg]
    #pragma unroll
    for (int mt = 0; mt < 2; ++mt)
        #pragma unroll
        for (int nt = 0; nt < 4; ++nt)
            #pragma unroll
            for (int r = 0; r < 4; ++r) acc[mt][nt][r] = 0.f;

    for (int lc = 0; lc < NCH; ++lc) {
        const int gc = CB + lc;
        const uint32_t Astg = smb + SM_A0 + gid * A_GRP + (lc & 1) * A_STG;
        const uint32_t Bstg = smb + SM_B0 + gid * B_GRP + (lc & 1) * B_STG;

        // STS A(lc) from prefetch regs: bf16 hi/lo, swizzled
        {
            uint32_t h[8], l[8];
            #pragma unroll
            for (int i = 0; i < 4; ++i) {
                cvt_split(areg[i].x, areg[i].y, h[2*i],   l[2*i]);
                cvt_split(areg[i].z, areg[i].w, h[2*i+1], l[2*i+1]);
            }
            uint32_t o0 = SW128((uint32_t)(g_row * 128 + g_q * 32));
            uint32_t o1 = SW128((uint32_t)(g_row * 128 + g_q * 32 + 16));
            char* Abase = dsm + SM_A0 + gid * A_GRP + (lc & 1) * A_STG;
            *(uint4*)(Abase + o0)        = make_uint4(h[0], h[1], h[2], h[3]);
            *(uint4*)(Abase + o1)        = make_uint4(h[4], h[5], h[6], h[7]);
            *(uint4*)(Abase + 8192 + o0) = make_uint4(l[0], l[1], l[2], l[3]);
            *(uint4*)(Abase + 8192 + o1) = make_uint4(l[4], l[5], l[6], l[7]);
        }
        // prefetch A regs for chunk lc+1
        if (lc + 1 < NCH) {
            int fid = idx_s[g_row * K3 + gc + 1];
            const float4* src = (fid >= 0)
                ? (const float4*)(feat + (size_t)fid * CIN + g_q * 16) : nullptr;
            #pragma unroll
            for (int i = 0; i < 4; ++i)
                areg[i] = src ? src[i] : make_float4(0.f, 0.f, 0.f, 0.f);
        }

        // group barrier: A(lc) visible; all group warps finished compute(lc-1)
        BARG(gid);

        // refill B stage (lc+1)&1 with chunk lc+1 (stage free: compute(lc-1)
        // done). Chunks 0,1 prefilled, so start at lc>=1.
        if (ltid == 0 && lc >= 1 && lc + 1 < NCH) {
            int nc = lc + 1;
            uint32_t mb = smb + SM_MBAR + (gid * 2 + (nc & 1)) * 8;
            uint32_t bd = smb + SM_B0 + gid * B_GRP + (nc & 1) * B_STG;
            mbar_expect_tx(mb, 32768);
            bulk_g2s(bd,         g_Wpk[CB + nc][0], 16384, mb);
            bulk_g2s(bd + 16384, g_Wpk[CB + nc][1], 16384, mb);
        }

        mbar_wait(smb + SM_MBAR + (gid * 2 + (lc & 1)) * 8, (lc >> 1) & 1);

        // compute: 4 k16-steps
        const uint32_t Ah = Astg, Al = Astg + 8192;
        const uint32_t Bh = Bstg, Bl = Bstg + 16384;
        #pragma unroll
        for (int ks = 0; ks < 4; ++ks) {
            uint32_t ah[2][4], al[2][4], bh[4][2], bl[4][2];
            const uint32_t akb = ks * 32 + akc;
            const uint32_t bkb = ks * 32 + bkc;
            #pragma unroll
            for (int mt = 0; mt < 2; ++mt) {
                LDSM4(ah[mt][0], ah[mt][1], ah[mt][2], ah[mt][3],
                      Ah + arow[mt] + (akb ^ axor[mt]));
                LDSM4(al[mt][0], al[mt][1], al[mt][2], al[mt][3],
                      Al + arow[mt] + (akb ^ axor[mt]));
            }
            #pragma unroll
            for (int pt = 0; pt < 2; ++pt) {
                LDSM4(bh[2*pt][0], bh[2*pt][1], bh[2*pt+1][0], bh[2*pt+1][1],
                      Bh + brow[pt] + (bkb ^ bxor[pt]));
                LDSM4(bl[2*pt][0], bl[2*pt][1], bl[2*pt+1][0], bl[2*pt+1][1],
                      Bl + brow[pt] + (bkb ^ bxor[pt]));
            }
            #pragma unroll
            for (int mt = 0; mt < 2; ++mt)
                #pragma unroll
                for (int nt = 0; nt < 4; ++nt) {
                    MMA16816(acc[mt][nt], ah[mt], bh[nt]);
                    MMA16816(acc[mt][nt], ah[mt], bl[nt]);
                    MMA16816(acc[mt][nt], al[mt], bh[nt]);
                }
        }
    }

    // --- cross-group reduction -----------------------------------------------
    __syncthreads();                        // all pipelines done; reuse A area
    float* const Red = (float*)(dsm + SM_A0);
    if (gid == 1) {                         // group 1 spills partials
        #pragma unroll
        for (int mt = 0; mt < 2; ++mt) {
            int r0 = wm * 32 + mt * 16 + (lane >> 2);
            #pragma unroll
            for (int nt = 0; nt < 4; ++nt) {
                int cb = wn * 32 + nt * 8 + (lane & 3) * 2;
                *(float2*)(Red + r0 * COUT + cb) =
                    make_float2(acc[mt][nt][0], acc[mt][nt][1]);
                *(float2*)(Red + (r0 + 8) * COUT + cb) =
                    make_float2(acc[mt][nt][2], acc[mt][nt][3]);
            }
        }
    }
    __syncthreads();
    if (gid == 0) {                         // group 0 adds its partials (RMW)
        #pragma unroll
        for (int mt = 0; mt < 2; ++mt) {
            int r0 = wm * 32 + mt * 16 + (lane >> 2);
            #pragma unroll
            for (int nt = 0; nt < 4; ++nt) {
                int cb = wn * 32 + nt * 8 + (lane & 3) * 2;
                float2 v0 = *(float2*)(Red + r0 * COUT + cb);
                float2 v1 = *(float2*)(Red + (r0 + 8) * COUT + cb);
                v0.x += acc[mt][nt][0]; v0.y += acc[mt][nt][1];
                v1.x += acc[mt][nt][2]; v1.y += acc[mt][nt][3];
                *(float2*)(Red + r0 * COUT + cb)       = v0;
                *(float2*)(Red + (r0 + 8) * COUT + cb) = v1;
            }
        }
    }
    __syncthreads();

    // --- LayerNorm + ReLU: 512 threads, row = tid>>3, q = tid&7 (16 cols) ---
    {
        const int row = tid >> 3;
        const int q   = tid & 7;
        const float* rrow = Red + row * COUT + q * 16;
        float4 v[4];
        float s = 0.f, sq = 0.f;
        #pragma unroll
        for (int i = 0; i < 4; ++i) {
            v[i] = ((const float4*)rrow)[i];
            s  += v[i].x + v[i].y + v[i].z + v[i].w;
            sq += v[i].x*v[i].x + v[i].y*v[i].y + v[i].z*v[i].z + v[i].w*v[i].w;
        }
        s  += __shfl_xor_sync(0xffffffffu, s, 1);
        sq += __shfl_xor_sync(0xffffffffu, sq, 1);
        s  += __shfl_xor_sync(0xffffffffu, s, 2);
        sq += __shfl_xor_sync(0xffffffffu, sq, 2);
        s  += __shfl_xor_sync(0xffffffffu, s, 4);
        sq += __shfl_xor_sync(0xffffffffu, sq, 4);
        float mu  = s * (1.f / COUT);
        float var = sq * (1.f / COUT) - mu * mu;
        float inv = rsqrtf(var + EPS);
        int valid = val_s[row];
        int gr = base + row;
        const float* gs = (const float*)(dsm + SM_GAMMA) + q * 16;
        const float* bs = (const float*)(dsm + SM_BETA)  + q * 16;
        float* orow = out_feat + (size_t)gr * COUT + q * 16;
        #pragma unroll
        for (int i = 0; i < 4; ++i) {
            float4 o;
            o.x = fmaxf(0.f, (v[i].x - mu) * inv * gs[4*i+0] + bs[4*i+0]);
            o.y = fmaxf(0.f, (v[i].y - mu) * inv * gs[4*i+1] + bs[4*i+1]);
            o.z = fmaxf(0.f, (v[i].z - mu) * inv * gs[4*i+2] + bs[4*i+2]);
            o.w = fmaxf(0.f, (v[i].w - mu) * inv * gs[4*i+3] + bs[4*i+3]);
            if (!valid) o = make_float4(0.f, 0.f, 0.f, 0.f);
            ((float4*)orow)[i] = o;
        }
    }

    // --- coords (col0 unconditional per reference quirk; xyz masked) --------
    if (tid < TR) {
        int gr = base + tid;
        int b  = gr >> KP_LOG2;
        int src = src_s[tid];
        float col0 = (b < B - 1) ? (float)(b + 1) : 0.f;
        float4 o;
        o.x = col0;
        if (val_s[tid]) {
            o.y = cc[(size_t)src * 3 + 0];
            o.z = cc[(size_t)src * 3 + 1];
            o.w = cc[(size_t)src * 3 + 2];
        } else {
            o.y = 0.f; o.z = 0.f; o.w = 0.f;
        }
        ((float4*)out_coor)[gr] = o;
    }

    __syncthreads();
    if (tid == 0) {
        #pragma unroll
        for (int s = 0; s < 4; ++s) mbar_inval(smb + SM_MBAR + s * 8);
    }
}

extern "C" void kernel_launch(void* const* d_in, const int* in_sizes, int n_in,
                              void* d_out, int out_size)
{
    const float* feat     = (const float*)d_in[0];
    const float* cc       = (const float*)d_in[1];
    const int*   vidx     = (const int*)d_in[2];     // int32 (JAX x64 disabled)
    const int*   num_list = (const int*)d_in[3];
    const float* W        = (const float*)d_in[4];
    const float* gamma    = (const float*)d_in[5];
    const float* beta     = (const float*)d_in[6];

    int Nfeat = in_sizes[0] / CIN;   // 200000
    int M     = in_sizes[1] / 3;     // 40000
    int B     = in_sizes[3];         // 4
    int totalRows = B * KP;          // 8192

    float* out_feat = (float*)d_out;
    float* out_coor = out_feat + (size_t)totalRows * COUT;

    cudaFuncSetAttribute(fused_mma_ln,
                         cudaFuncAttributeMaxDynamicSharedMemorySize, SMEM_TOTAL);

    prep_w<<<K3, 256>>>(W);
    fused_mma_ln<<<totalRows / TR, NT, SMEM_TOTAL>>>(feat, vidx, gamma, beta,
                                                     num_list, cc, out_feat,
                                                     out_coor, Nfeat, M, B,
                                                     totalRows);
}

// round 14
// speedup vs baseline: 1.7333x; 1.3440x over previous
#include <cuda_runtime.h>
#include <cuda_fp16.h>
#include <stdint.h>

// ---------------------------------------------------------------------------
// DynamicPointConvBackBone, single-pass fp16 mma.sync edition.
// D[8192,128] = gather(A)[8192,1728] @ W[1728,128], computed as
//   fp16(A) @ fp16(W*1024) * (1/1024)   (f32 accumulate)
// fp16 rounding gives dot rel-err ~3e-4 << 1e-3 gate; W pre-scaled by 1024 so
// all entries are normal fp16 (raw |W|~1e-4 would hit subnormals).
// 128 CTAs x 512 thr = 2 groups x 8 warps (split-K: chunks 0-12 / 13-26).
// Per group: 2-stage A (STS), 4-stage B (cp.async.bulk) pipelines, own
// mbarriers + named barrier. Warp tile 32x32 (2M x 4N). Smem reduction + LN.
// ---------------------------------------------------------------------------

#define K3      27
#define CIN     64
#define COUT    128
#define KP      2048
#define KP_LOG2 11
#define TR      64
#define NT      512
#define EPS     1e-3f
#define WSCL    1024.0f
#define ISCL    (1.0f / 1024.0f)

#define SW128(o) ((o) ^ (((o) >> 3) & 0x70))

// ---- dynamic smem layout (bytes) ----
#define SM_MBAR   0        // 8 x 8B (group*4 + stage)
#define SM_NL     64
#define SM_SRC    96       // 64 ints
#define SM_VAL    352
#define SM_GAMMA  608      // 128 f32
#define SM_BETA   1120
#define SM_IDX    1632     // 64*27*4 = 6912 -> ends 8544
#define SM_A0     9216     // per group: 2 stages x 8KB
#define A_STG     8192
#define A_GRP     16384
#define SM_B0     41984    // per group: 4 stages x 16KB
#define B_STG     16384
#define B_GRP     65536
#define SMEM_TOTAL (SM_B0 + 2 * B_GRP)   // 173056 (169KB)

// W packed: [chunk][16KB pre-swizzled fp16 tile: n rows x 64 k], scaled x1024
__device__ __align__(1024) uint8_t g_Wpk[K3][16384];

__device__ __forceinline__ uint32_t smem_u32(const void* p) {
    uint32_t a;
    asm("{ .reg .u64 t; cvta.to.shared.u64 t, %1; cvt.u32.u64 %0, t; }"
        : "=r"(a) : "l"(p));
    return a;
}
__device__ __forceinline__ void mbar_init(uint32_t a, uint32_t cnt) {
    asm volatile("mbarrier.init.shared.b64 [%0], %1;" :: "r"(a), "r"(cnt) : "memory");
}
__device__ __forceinline__ void mbar_inval(uint32_t a) {
    asm volatile("mbarrier.inval.shared.b64 [%0];" :: "r"(a) : "memory");
}
__device__ __forceinline__ void mbar_expect_tx(uint32_t a, uint32_t tx) {
    asm volatile("mbarrier.arrive.expect_tx.shared.b64 _, [%0], %1;"
                 :: "r"(a), "r"(tx) : "memory");
}
__device__ __forceinline__ void mbar_wait(uint32_t a, uint32_t parity) {
    asm volatile(
        "{\n\t.reg .pred P;\n\t"
        "W_%=:\n\t"
        "mbarrier.try_wait.parity.acquire.cta.shared::cta.b64 P, [%0], %1, 0x989680;\n\t"
        "@P bra D_%=;\n\t"
        "bra.uni W_%=;\n\t"
        "D_%=:\n\t}"
        :: "r"(a), "r"(parity) : "memory");
}
__device__ __forceinline__ void bulk_g2s(uint32_t dst, const void* src,
                                         uint32_t bytes, uint32_t mbar) {
    asm volatile(
        "cp.async.bulk.shared::cta.global.mbarrier::complete_tx::bytes "
        "[%0], [%1], %2, [%3];"
        :: "r"(dst), "l"(src), "r"(bytes), "r"(mbar) : "memory");
}
#define BARG(gid) \
    asm volatile("bar.sync %0, 256;" :: "r"((gid) + 1) : "memory")
#define LDSM4(r0, r1, r2, r3, addr) \
    asm volatile("ldmatrix.sync.aligned.m8n8.x4.shared.b16 {%0,%1,%2,%3}, [%4];" \
                 : "=r"(r0), "=r"(r1), "=r"(r2), "=r"(r3) : "r"(addr))
#define MMA16816F(d, a, b) \
    asm volatile("mma.sync.aligned.m16n8k16.row.col.f32.f16.f16.f32 " \
                 "{%0,%1,%2,%3}, {%4,%5,%6,%7}, {%8,%9}, {%0,%1,%2,%3};" \
                 : "+f"((d)[0]), "+f"((d)[1]), "+f"((d)[2]), "+f"((d)[3]) \
                 : "r"((a)[0]), "r"((a)[1]), "r"((a)[2]), "r"((a)[3]), \
                   "r"((b)[0]), "r"((b)[1]))

__device__ __forceinline__ uint32_t pack_h2(float a, float b) {
    __half2 h = __float22half2_rn(make_float2(a, b));
    return *(uint32_t*)&h;
}

// ---------------- prep: W[k][n] f32 -> g_Wpk[c][SW128(n*128+k*2)] fp16*1024 --
__global__ void prep_w(const float* __restrict__ W) {
    __shared__ float sw[64 * 129];
    const int c   = blockIdx.x;
    const int tid = threadIdx.x;
    const float2* src = (const float2*)(W + (size_t)c * 64 * COUT);
    for (int i = tid; i < 64 * COUT / 2; i += 256) {
        float2 v = src[i];
        int k = (2 * i) >> 7, n = (2 * i) & 127;
        sw[k * 129 + n]     = v.x;
        sw[k * 129 + n + 1] = v.y;
    }
    __syncthreads();
    for (int t = tid; t < 1024; t += 256) {
        int kh = t & 7, n = t >> 3;
        uint32_t h[4];
        #pragma unroll
        for (int i = 0; i < 4; ++i) {
            float a = sw[(kh * 8 + 2 * i)     * 129 + n] * WSCL;
            float b = sw[(kh * 8 + 2 * i + 1) * 129 + n] * WSCL;
            h[i] = pack_h2(a, b);
        }
        uint32_t off = SW128((uint32_t)(n * 128 + kh * 16));
        *(uint4*)(&g_Wpk[c][off]) = make_uint4(h[0], h[1], h[2], h[3]);
    }
}

// ---------------- main fused kernel ----------------
__global__ __launch_bounds__(NT, 1)
void fused_mma_ln(const float* __restrict__ feat,
                  const int* __restrict__ vidx,
                  const float* __restrict__ gamma,
                  const float* __restrict__ beta,
                  const int* __restrict__ num_list,
                  const float* __restrict__ cc,
                  float* __restrict__ out_feat,
                  float* __restrict__ out_coor,
                  int Nfeat, int M, int B, int totalRows)
{
    extern __shared__ char dsm[];
    const uint32_t smb = smem_u32(dsm);
    const int tid  = threadIdx.x;
    const int gid  = tid >> 8;          // group 0/1
    const int ltid = tid & 255;
    const int lane = tid & 31;
    const int base = blockIdx.x * TR;

    const int CB  = gid ? 13 : 0;       // first chunk of this group
    const int NCH = gid ? 14 : 13;      // chunks in this group

    int* const nl_s  = (int*)(dsm + SM_NL);
    int* const src_s = (int*)(dsm + SM_SRC);
    int* const val_s = (int*)(dsm + SM_VAL);
    int* const idx_s = (int*)(dsm + SM_IDX);

    if (tid == 0) {
        #pragma unroll
        for (int s = 0; s < 8; ++s) mbar_init(smb + SM_MBAR + s * 8, 1);
        #pragma unroll 4
        for (int i = 0; i < B && i < 8; ++i) nl_s[i] = num_list[i];
    }
    if (tid < COUT) {
        ((float*)(dsm + SM_GAMMA))[tid] = gamma[tid];
        ((float*)(dsm + SM_BETA))[tid]  = beta[tid];
    }
    __syncthreads();

    // --- per-row source voxel + validity ------------------------------------
    if (tid < TR) {
        int gr = base + tid;
        int b = gr >> KP_LOG2;
        int j = gr & (KP - 1);
        int off = 0;
        #pragma unroll 4
        for (int i = 0; i < b; ++i) off += nl_s[i];
        int nl = nl_s[b];
        int src = off + j;
        if (src > M - 1) src = M - 1;
        if (src < 0)     src = 0;
        src_s[tid] = src;
        val_s[tid] = (j < nl) ? 1 : 0;
    }
    __syncthreads();

    // --- neighbor indices ---------------------------------------------------
    for (int e = tid; e < TR * K3; e += NT) {
        int r = e / K3, k = e - r * K3;
        int raw = vidx[(size_t)src_s[r] * K3 + k];
        int v = raw;
        if (raw < 0) v = -1;
        else if (v > Nfeat - 1) v = Nfeat - 1;
        idx_s[e] = v;
    }
    __syncthreads();

    // --- kick off this group's B copies for local chunks 0..3 ---------------
    if (ltid == 0) {
        #pragma unroll
        for (int s = 0; s < 4; ++s) {
            uint32_t mb = smb + SM_MBAR + (gid * 4 + s) * 8;
            uint32_t bd = smb + SM_B0 + gid * B_GRP + s * B_STG;
            mbar_expect_tx(mb, B_STG);
            bulk_g2s(bd, g_Wpk[CB + s], B_STG, mb);
        }
    }

    // --- A gather mapping: row = ltid>>2, quarter q = ltid&3 (16 ch) --------
    const int g_row = ltid >> 2;
    const int g_q   = ltid & 3;

    float4 areg[4];
    {
        int fid = idx_s[g_row * K3 + CB];
        const float4* src = (fid >= 0)
            ? (const float4*)(feat + (size_t)fid * CIN + g_q * 16) : nullptr;
        #pragma unroll
        for (int i = 0; i < 4; ++i)
            areg[i] = src ? src[i] : make_float4(0.f, 0.f, 0.f, 0.f);
    }

    // --- warp tiling within group: 2M x 4N, warp tile 32x32 -----------------
    const int gwid = (tid >> 5) & 7;
    const int wm = gwid & 1;          // rows wm*32 .. +31
    const int wn = gwid >> 1;         // cols wn*32 .. +31
    const int m_  = lane >> 3;
    const int ri  = lane & 7;

    uint32_t arow[2], axor[2];
    #pragma unroll
    for (int mt = 0; mt < 2; ++mt) {
        uint32_t rp = (uint32_t)(wm * 32 + mt * 16 + (m_ & 1) * 8 + ri) * 128;
        arow[mt] = rp;
        axor[mt] = (rp >> 3) & 0x70;
    }
    const uint32_t akc = ((lane >> 4) & 1) * 16;
    uint32_t brow[2], bxor[2];
    #pragma unroll
    for (int pt = 0; pt < 2; ++pt) {
        uint32_t rp = (uint32_t)(wn * 32 + pt * 16 + ((lane >> 4) & 1) * 8 + ri) * 128;
        brow[pt] = rp;
        bxor[pt] = (rp >> 3) & 0x70;
    }
    const uint32_t bkc = ((lane >> 3) & 1) * 16;

    float acc[2][4][4];               // [mt][nt][reg]
    #pragma unroll
    for (int mt = 0; mt < 2; ++mt)
        #pragma unroll
        for (int nt = 0; nt < 4; ++nt)
            #pragma unroll
            for (int r = 0; r < 4; ++r) acc[mt][nt][r] = 0.f;

    for (int lc = 0; lc < NCH; ++lc) {
        const int gc = CB + lc;
        const uint32_t Astg = smb + SM_A0 + gid * A_GRP + (lc & 1) * A_STG;
        const uint32_t Bstg = smb + SM_B0 + gid * B_GRP + (lc & 3) * B_STG;

        // STS A(lc) from prefetch regs: fp16, swizzled
        {
            uint32_t h[8];
            #pragma unroll
            for (int i = 0; i < 4; ++i) {
                h[2*i]   = pack_h2(areg[i].x, areg[i].y);
                h[2*i+1] = pack_h2(areg[i].z, areg[i].w);
            }
            uint32_t o0 = SW128((uint32_t)(g_row * 128 + g_q * 32));
            uint32_t o1 = SW128((uint32_t)(g_row * 128 + g_q * 32 + 16));
            char* Abase = dsm + SM_A0 + gid * A_GRP + (lc & 1) * A_STG;
            *(uint4*)(Abase + o0) = make_uint4(h[0], h[1], h[2], h[3]);
            *(uint4*)(Abase + o1) = make_uint4(h[4], h[5], h[6], h[7]);
        }
        // prefetch A regs for chunk lc+1
        if (lc + 1 < NCH) {
            int fid = idx_s[g_row * K3 + gc + 1];
            const float4* src = (fid >= 0)
                ? (const float4*)(feat + (size_t)fid * CIN + g_q * 16) : nullptr;
            #pragma unroll
            for (int i = 0; i < 4; ++i)
                areg[i] = src ? src[i] : make_float4(0.f, 0.f, 0.f, 0.f);
        }

        // group barrier: A(lc) visible; all group warps finished compute(lc-1)
        BARG(gid);

        // refill B stage (lc+3)&3 == (lc-1)&3, just freed by compute(lc-1)
        if (ltid == 0 && lc >= 1 && lc + 3 < NCH) {
            int nc = lc + 3;
            uint32_t mb = smb + SM_MBAR + (gid * 4 + (nc & 3)) * 8;
            uint32_t bd = smb + SM_B0 + gid * B_GRP + (nc & 3) * B_STG;
            mbar_expect_tx(mb, B_STG);
            bulk_g2s(bd, g_Wpk[CB + nc], B_STG, mb);
        }

        mbar_wait(smb + SM_MBAR + (gid * 4 + (lc & 3)) * 8, (lc >> 2) & 1);

        // compute: 4 k16-steps, single fp16 pass
        #pragma unroll
        for (int ks = 0; ks < 4; ++ks) {
            uint32_t ah[2][4], bh[4][2];
            const uint32_t akb = ks * 32 + akc;
            const uint32_t bkb = ks * 32 + bkc;
            #pragma unroll
            for (int mt = 0; mt < 2; ++mt)
                LDSM4(ah[mt][0], ah[mt][1], ah[mt][2], ah[mt][3],
                      Astg + arow[mt] + (akb ^ axor[mt]));
            #pragma unroll
            for (int pt = 0; pt < 2; ++pt)
                LDSM4(bh[2*pt][0], bh[2*pt][1], bh[2*pt+1][0], bh[2*pt+1][1],
                      Bstg + brow[pt] + (bkb ^ bxor[pt]));
            #pragma unroll
            for (int mt = 0; mt < 2; ++mt)
                #pragma unroll
                for (int nt = 0; nt < 4; ++nt)
                    MMA16816F(acc[mt][nt], ah[mt], bh[nt]);
        }
    }

    // --- cross-group reduction (scale by 1/1024 at spill/add) ----------------
    __syncthreads();                        // all pipelines done; reuse A+B area
    float* const Red = (float*)(dsm + SM_A0);
    if (gid == 1) {                         // group 1 spills scaled partials
        #pragma unroll
        for (int mt = 0; mt < 2; ++mt) {
            int r0 = wm * 32 + mt * 16 + (lane >> 2);
            #pragma unroll
            for (int nt = 0; nt < 4; ++nt) {
                int cb = wn * 32 + nt * 8 + (lane & 3) * 2;
                *(float2*)(Red + r0 * COUT + cb) =
                    make_float2(acc[mt][nt][0] * ISCL, acc[mt][nt][1] * ISCL);
                *(float2*)(Red + (r0 + 8) * COUT + cb) =
                    make_float2(acc[mt][nt][2] * ISCL, acc[mt][nt][3] * ISCL);
            }
        }
    }
    __syncthreads();
    if (gid == 0) {                         // group 0 adds its scaled partials
        #pragma unroll
        for (int mt = 0; mt < 2; ++mt) {
            int r0 = wm * 32 + mt * 16 + (lane >> 2);
            #pragma unroll
            for (int nt = 0; nt < 4; ++nt) {
                int cb = wn * 32 + nt * 8 + (lane & 3) * 2;
                float2 v0 = *(float2*)(Red + r0 * COUT + cb);
                float2 v1 = *(float2*)(Red + (r0 + 8) * COUT + cb);
                v0.x += acc[mt][nt][0] * ISCL; v0.y += acc[mt][nt][1] * ISCL;
                v1.x += acc[mt][nt][2] * ISCL; v1.y += acc[mt][nt][3] * ISCL;
                *(float2*)(Red + r0 * COUT + cb)       = v0;
                *(float2*)(Red + (r0 + 8) * COUT + cb) = v1;
            }
        }
    }
    __syncthreads();

    // --- LayerNorm + ReLU: 512 threads, row = tid>>3, q = tid&7 (16 cols) ---
    {
        const int row = tid >> 3;
        const int q   = tid & 7;
        const float* rrow = Red + row * COUT + q * 16;
        float4 v[4];
        float s = 0.f, sq = 0.f;
        #pragma unroll
        for (int i = 0; i < 4; ++i) {
            v[i] = ((const float4*)rrow)[i];
            s  += v[i].x + v[i].y + v[i].z + v[i].w;
            sq += v[i].x*v[i].x + v[i].y*v[i].y + v[i].z*v[i].z + v[i].w*v[i].w;
        }
        s  += __shfl_xor_sync(0xffffffffu, s, 1);
        sq += __shfl_xor_sync(0xffffffffu, sq, 1);
        s  += __shfl_xor_sync(0xffffffffu, s, 2);
        sq += __shfl_xor_sync(0xffffffffu, sq, 2);
        s  += __shfl_xor_sync(0xffffffffu, s, 4);
        sq += __shfl_xor_sync(0xffffffffu, sq, 4);
        float mu  = s * (1.f / COUT);
        float var = sq * (1.f / COUT) - mu * mu;
        float inv = rsqrtf(var + EPS);
        int valid = val_s[row];
        int gr = base + row;
        const float* gs = (const float*)(dsm + SM_GAMMA) + q * 16;
        const float* bs = (const float*)(dsm + SM_BETA)  + q * 16;
        float* orow = out_feat + (size_t)gr * COUT + q * 16;
        #pragma unroll
        for (int i = 0; i < 4; ++i) {
            float4 o;
            o.x = fmaxf(0.f, (v[i].x - mu) * inv * gs[4*i+0] + bs[4*i+0]);
            o.y = fmaxf(0.f, (v[i].y - mu) * inv * gs[4*i+1] + bs[4*i+1]);
            o.z = fmaxf(0.f, (v[i].z - mu) * inv * gs[4*i+2] + bs[4*i+2]);
            o.w = fmaxf(0.f, (v[i].w - mu) * inv * gs[4*i+3] + bs[4*i+3]);
            if (!valid) o = make_float4(0.f, 0.f, 0.f, 0.f);
            ((float4*)orow)[i] = o;
        }
    }

    // --- coords (col0 unconditional per reference quirk; xyz masked) --------
    if (tid < TR) {
        int gr = base + tid;
        int b  = gr >> KP_LOG2;
        int src = src_s[tid];
        float col0 = (b < B - 1) ? (float)(b + 1) : 0.f;
        float4 o;
        o.x = col0;
        if (val_s[tid]) {
            o.y = cc[(size_t)src * 3 + 0];
            o.z = cc[(size_t)src * 3 + 1];
            o.w = cc[(size_t)src * 3 + 2];
        } else {
            o.y = 0.f; o.z = 0.f; o.w = 0.f;
        }
        ((float4*)out_coor)[gr] = o;
    }

    __syncthreads();
    if (tid == 0) {
        #pragma unroll
        for (int s = 0; s < 8; ++s) mbar_inval(smb + SM_MBAR + s * 8);
    }
}

extern "C" void kernel_launch(void* const* d_in, const int* in_sizes, int n_in,
                              void* d_out, int out_size)
{
    const float* feat     = (const float*)d_in[0];
    const float* cc       = (const float*)d_in[1];
    const int*   vidx     = (const int*)d_in[2];     // int32 (JAX x64 disabled)
    const int*   num_list = (const int*)d_in[3];
    const float* W        = (const float*)d_in[4];
    const float* gamma    = (const float*)d_in[5];
    const float* beta     = (const float*)d_in[6];

    int Nfeat = in_sizes[0] / CIN;   // 200000
    int M     = in_sizes[1] / 3;     // 40000
    int B     = in_sizes[3];         // 4
    int totalRows = B * KP;          // 8192

    float* out_feat = (float*)d_out;
    float* out_coor = out_feat + (size_t)totalRows * COUT;

    cudaFuncSetAttribute(fused_mma_ln,
                         cudaFuncAttributeMaxDynamicSharedMemorySize, SMEM_TOTAL);

    prep_w<<<K3, 256>>>(W);
    fused_mma_ln<<<totalRows / TR, NT, SMEM_TOTAL>>>(feat, vidx, gamma, beta,
                                                     num_list, cc, out_feat,
                                                     out_coor, Nfeat, M, B,
                                                     totalRows);
}